// round 17
// baseline (speedup 1.0000x reference)
#include <cuda_runtime.h>
#include <cstdint>

// SimplifiedEncoder: 2-layer weight-shared LSTM, SEQ=512, B=128, D=1024.
// ONE persistent kernel. Per cell: C[128x4096] = A[128x2048] @ Wcat^T,
// split across 128 CTAs = 16 n_tiles x 8 k_splits. tf32 mma.sync m16n8k8.
// R16 changes vs R13 (operand-feed stalls fix):
//   - all tf32 mirrors stored k-pair-PERMUTED (slot=((k&3)<<1)|(k>>2) within
//     each 8-block) so every mma fragment pair (k,k+4) is one LDS.64
//     -> 12 shared loads per warp per k8 instead of 24 scalar
//   - epilogue vectorized (float2 partial loads/stores, single pass)
// Arithmetic is bit-identical to R13 (storage order only).

#define BATCH  128
#define DIM    1024
#define BD     (BATCH * DIM)
#define SEQL   512
#define NCTA   128
#define NTHR   512
#define KC     32
#define NSTG   8          // 256 K per split / KC
#define LDS_S  36         // smem row stride (u32)
#define VOCAB  32000

// ---- persistent fp32 state ----
__device__ float g_h [BD];
__device__ float g_c [BD];
__device__ float g_h2[BD];
__device__ float g_c2[BD];
__device__ float g_h1[BD];
__device__ float g_c1[BD];
__device__ float g_bias[4 * DIM];
__device__ float g_P[8][BATCH][4 * DIM];       // split-K partials (16 MB)
// ---- tf32-bit operand mirrors (k-pair permuted) ----
__device__ uint32_t g_ht  [BD];
__device__ uint32_t g_h2t [BD];
__device__ uint32_t g_h1t [BD];
__device__ uint32_t g_embt[(size_t)VOCAB * DIM];   // 131 MB
__device__ uint32_t g_Wiht[(size_t)4 * DIM * DIM]; // 16.8 MB
__device__ uint32_t g_Whht[(size_t)4 * DIM * DIM];
__device__ unsigned g_barGen = 0;              // monotonic across replays
__device__ unsigned g_barCnt = 0;

// ---- helpers ----
__device__ __forceinline__ void cp16(uint32_t* sdst, const uint32_t* gsrc) {
    unsigned s = (unsigned)__cvta_generic_to_shared(sdst);
    asm volatile("cp.async.cg.shared.global [%0], [%1], 16;\n" :: "r"(s), "l"(gsrc));
}
__device__ __forceinline__ void cp_commit() { asm volatile("cp.async.commit_group;\n"); }
__device__ __forceinline__ void cp_wait1()  { asm volatile("cp.async.wait_group 1;\n" ::: "memory"); }
__device__ __forceinline__ void cp_wait0()  { asm volatile("cp.async.wait_group 0;\n" ::: "memory"); }

__device__ __forceinline__ uint32_t tf32r(float v) {
    uint32_t r; asm("cvt.rna.tf32.f32 %0, %1;" : "=r"(r) : "f"(v)); return r;
}
// permuted index within flat arrays whose row length is a multiple of 8
__device__ __forceinline__ int pflat(int i) {
    return (i & ~7) | ((i & 3) << 1) | ((i >> 2) & 1);
}
__device__ __forceinline__ void mma8(float* d, const uint32_t* a, uint32_t b0, uint32_t b1) {
    asm volatile(
        "mma.sync.aligned.m16n8k8.row.col.f32.tf32.tf32.f32 "
        "{%0,%1,%2,%3}, {%4,%5,%6,%7}, {%8,%9}, {%0,%1,%2,%3};\n"
        : "+f"(d[0]), "+f"(d[1]), "+f"(d[2]), "+f"(d[3])
        : "r"(a[0]), "r"(a[1]), "r"(a[2]), "r"(a[3]), "r"(b0), "r"(b1));
}
__device__ __forceinline__ float sigf(float x)   { return __fdividef(1.0f, 1.0f + __expf(-x)); }
__device__ __forceinline__ float tanh_f(float x) { return __fmaf_rn(2.0f, sigf(2.0f * x), -1.0f); }

// Grid barrier, replay-safe monotonic generation.
__device__ __forceinline__ void gridbar(unsigned target) {
    __syncthreads();
    if (threadIdx.x == 0) {
        __threadfence();
        if (atomicAdd(&g_barCnt, 1u) == NCTA - 1u) {
            g_barCnt = 0u;
            __threadfence();
            atomicExch(&g_barGen, target);
        } else {
            while ((int)(*(volatile unsigned*)&g_barGen) - (int)target < 0) { }
        }
        __threadfence();
    }
    __syncthreads();
}

// ---- GEMM phase: partial [128 x 256] over a 256-wide K slice ----
// splits 0-3: first A-half (emb|h1) with Wih; 4-7: second half (h|h2) with Whh.
template<int LAYER>
__device__ void gemm_phase(uint32_t* As, uint32_t* Ws, const uint32_t** Abase,
                           const int* __restrict__ xt)
{
    const int tid = threadIdx.x;
    const int nt  = blockIdx.x & 15;
    const int ks  = blockIdx.x >> 4;
    const int n0  = nt * 256;
    const bool hi = (ks >= 4);
    const int koff = (ks & 3) * 256;

    if (tid < BATCH) {
        const uint32_t* b;
        if (LAYER == 1) b = hi ? (g_ht   + tid * DIM + koff)
                               : (g_embt + (size_t)xt[tid] * DIM + koff);
        else            b = hi ? (g_h2t  + tid * DIM + koff)
                               : (g_h1t  + tid * DIM + koff);
        Abase[tid] = b;
    }
    const uint32_t* Wb0 = (hi ? g_Whht : g_Wiht) + (size_t)n0 * DIM + koff;
    __syncthreads();

    float acc[4][4][4];
    #pragma unroll
    for (int qm = 0; qm < 4; qm++)
        #pragma unroll
        for (int qn = 0; qn < 4; qn++)
            #pragma unroll
            for (int p = 0; p < 4; p++) acc[qm][qn][p] = 0.0f;

    auto prefetch = [&](int s) {
        uint32_t* ad = As + (s % 3) * (128 * LDS_S);
        uint32_t* wd = Ws + (s % 3) * (256 * LDS_S);
        const int kc = s * KC;
        #pragma unroll
        for (int i = 0; i < 2; i++) {                 // A: 1024 16B chunks
            int cc = tid + i * NTHR;
            int r = cc >> 3, col = (cc & 7) * 4;
            cp16(ad + r * LDS_S + col, Abase[r] + kc + col);
        }
        #pragma unroll
        for (int i = 0; i < 4; i++) {                 // W: 2048 chunks
            int cc = tid + i * NTHR;
            int r = cc >> 3, col = (cc & 7) * 4;
            cp16(wd + r * LDS_S + col, Wb0 + (size_t)r * DIM + kc + col);
        }
        cp_commit();
    };

    const int lane = tid & 31, warp = tid >> 5;
    const int grp  = lane >> 2, tig = lane & 3;
    const int mb   = (warp >> 3) * 64;   // 2 warps in M
    const int nb   = (warp & 7) * 32;    // 8 warps in N

    auto docompute = [&](int s) {
        const uint32_t* Ab  = As + (s % 3) * (128 * LDS_S);
        const uint32_t* Wsb = Ws + (s % 3) * (256 * LDS_S);
        #pragma unroll
        for (int k8 = 0; k8 < KC / 8; k8++) {
            const int kk = k8 * 8 + 2 * tig;          // pair slot for (k, k+4)
            uint32_t af[4][4];
            #pragma unroll
            for (int qm = 0; qm < 4; qm++) {
                const uint32_t* p = Ab + (mb + qm * 16 + grp) * LDS_S + kk;
                uint2 lo = *(const uint2*)p;                 // {a0, a2}
                uint2 hh = *(const uint2*)(p + 8 * LDS_S);   // {a1, a3}
                af[qm][0] = lo.x; af[qm][1] = hh.x;
                af[qm][2] = lo.y; af[qm][3] = hh.y;
            }
            uint2 bf[4];
            #pragma unroll
            for (int qn = 0; qn < 4; qn++)
                bf[qn] = *(const uint2*)(Wsb + (nb + qn * 8 + grp) * LDS_S + kk);
            #pragma unroll
            for (int qm = 0; qm < 4; qm++)
                #pragma unroll
                for (int qn = 0; qn < 4; qn++)
                    mma8(acc[qm][qn], af[qm], bf[qn].x, bf[qn].y);
        }
    };

    prefetch(0);
    prefetch(1);
    #pragma unroll 1
    for (int s = 0; s < NSTG; s++) {
        if (s == NSTG - 1) cp_wait0(); else cp_wait1();
        __syncthreads();                    // buf s visible; compute(s-1) drained
        if (s + 2 < NSTG) prefetch(s + 2);  // writes buf (s+2)%3, free since sync
        docompute(s);
    }

    float* Pks = &g_P[ks][0][0];
    #pragma unroll
    for (int qm = 0; qm < 4; qm++) {
        #pragma unroll
        for (int qn = 0; qn < 4; qn++) {
            const int b0  = mb + qm * 16 + grp;
            const int col = n0 + nb + qn * 8 + 2 * tig;
            *(float2*)(Pks + (size_t)b0 * 4096 + col) =
                make_float2(acc[qm][qn][0], acc[qm][qn][1]);
            *(float2*)(Pks + (size_t)(b0 + 8) * 4096 + col) =
                make_float2(acc[qm][qn][2], acc[qm][qn][3]);
        }
    }
}

// ---- reduction + LSTM epilogue. CTA = batch row; threads sweep j pairs. ----
template<int LAYER>
__device__ void epi_phase(const int* __restrict__ xt)
{
    const int b = blockIdx.x;
    const bool pad = (xt[b] == 0);
    const int j = threadIdx.x * 2;                 // 512 threads x 2 j = 1024
    float2 s[4];
    #pragma unroll
    for (int g = 0; g < 4; g++) {
        float2 a = *(const float2*)&g_bias[g * DIM + j];
        #pragma unroll
        for (int sp = 0; sp < 8; sp++) {
            float2 p = *(const float2*)&g_P[sp][b][g * DIM + j];
            a.x += p.x; a.y += p.y;
        }
        s[g] = a;
    }
    const int idx = b * DIM + j;
    if (LAYER == 1) {
        const float2 cold = *(const float2*)&g_c[idx];
        float2 cn, hn;
        {
            const float c0 = sigf(s[1].x) * cold.x + sigf(s[0].x) * tanh_f(s[2].x);
            cn.x = c0; hn.x = sigf(s[3].x) * tanh_f(c0);
            const float c1 = sigf(s[1].y) * cold.y + sigf(s[0].y) * tanh_f(s[2].y);
            cn.y = c1; hn.y = sigf(s[3].y) * tanh_f(c1);
        }
        *(float2*)&g_c1[idx] = cn;
        *(float2*)&g_h1[idx] = hn;
        g_h1t[pflat(idx)]     = tf32r(hn.x);
        g_h1t[pflat(idx + 1)] = tf32r(hn.y);
    } else {
        const float2 c2old = *(const float2*)&g_c2[idx];
        const float2 hold  = *(const float2*)&g_h[idx];
        const float2 cold  = *(const float2*)&g_c[idx];
        const float2 h1v   = *(const float2*)&g_h1[idx];
        const float2 c1v   = *(const float2*)&g_c1[idx];
        float2 hN, cN, h2N, c2N;
        {
            const float c2a = sigf(s[1].x) * c2old.x + sigf(s[0].x) * tanh_f(s[2].x);
            const float h2a = sigf(s[3].x) * tanh_f(c2a);
            hN.x  = pad ? hold.x : h1v.x;
            cN.x  = pad ? cold.x : c1v.x;
            h2N.x = pad ? hold.x : h2a;
            c2N.x = pad ? cold.x : c2a;
            const float c2b = sigf(s[1].y) * c2old.y + sigf(s[0].y) * tanh_f(s[2].y);
            const float h2b = sigf(s[3].y) * tanh_f(c2b);
            hN.y  = pad ? hold.y : h1v.y;
            cN.y  = pad ? cold.y : c1v.y;
            h2N.y = pad ? hold.y : h2b;
            c2N.y = pad ? cold.y : c2b;
        }
        *(float2*)&g_h [idx] = hN;
        *(float2*)&g_c [idx] = cN;
        *(float2*)&g_h2[idx] = h2N;
        *(float2*)&g_c2[idx] = c2N;
        g_ht [pflat(idx)]     = tf32r(hN.x);
        g_ht [pflat(idx + 1)] = tf32r(hN.y);
        g_h2t[pflat(idx)]     = tf32r(h2N.x);
        g_h2t[pflat(idx + 1)] = tf32r(h2N.y);
    }
}

// ---- single persistent kernel ----
__global__ void __launch_bounds__(NTHR, 1)
lstm_persist(const int*   __restrict__ x,
             const float* __restrict__ emb,
             const float* __restrict__ Wih,
             const float* __restrict__ Whh,
             const float* __restrict__ bih,
             const float* __restrict__ bhh,
             const float* __restrict__ h0,
             const float* __restrict__ c0,
             const float* __restrict__ h02,
             const float* __restrict__ c02,
             float* __restrict__ out)
{
    extern __shared__ uint32_t smu[];
    uint32_t* As = smu;                                 // [3][128*36]
    uint32_t* Ws = smu + 3 * 128 * LDS_S;               // [3][256*36]
    const uint32_t** Abase =
        (const uint32_t**)(smu + 3 * 128 * LDS_S + 3 * 256 * LDS_S);
    __shared__ unsigned sBase;

    const int tid = threadIdx.x;
    const int gt  = blockIdx.x * NTHR + tid;
    const int GT  = NCTA * NTHR;                        // 65536 threads

    if (tid == 0) sBase = atomicAdd(&g_barGen, 0u);

    // per-launch init (determinism across graph replays)
    for (int i = gt; i < BD; i += GT) {
        const int d = i & (DIM - 1);
        const float hv = h0[d], h2v = h02[d];
        g_h [i] = hv;   g_ht [pflat(i)] = tf32r(hv);
        g_c [i] = c0[d];
        g_h2[i] = h2v;  g_h2t[pflat(i)] = tf32r(h2v);
        g_c2[i] = c02[d];
    }
    if (gt < 4 * DIM) g_bias[gt] = bih[gt] + bhh[gt];
    // build k-pair-permuted tf32 mirrors (gather 4 scalars -> uint4 store).
    // dest slots s0..s0+3 within an 8-block take source k {0,4,1,5} or {2,6,3,7}.
    {
        auto build = [&](const float* src, uint32_t* dst, size_t n4) {
            for (size_t i = gt; i < n4; i += GT) {
                const size_t s0 = i * 4;
                const float* sp = src + (s0 & ~(size_t)7);
                uint4 v;
                if (s0 & 4) v = make_uint4(tf32r(__ldg(sp + 2)), tf32r(__ldg(sp + 6)),
                                           tf32r(__ldg(sp + 3)), tf32r(__ldg(sp + 7)));
                else        v = make_uint4(tf32r(__ldg(sp + 0)), tf32r(__ldg(sp + 4)),
                                           tf32r(__ldg(sp + 1)), tf32r(__ldg(sp + 5)));
                *(uint4*)(dst + s0) = v;
            }
        };
        build(emb, g_embt, (size_t)VOCAB * DIM / 4);
        build(Wih, g_Wiht, (size_t)4 * DIM * DIM / 4);
        build(Whh, g_Whht, (size_t)4 * DIM * DIM / 4);
    }
    __syncthreads();
    const unsigned base = sBase;
    unsigned bc = 0;
    gridbar(base + ++bc);

    for (int t = 0; t < SEQL; t++) {
        const int* xt = x + t * BATCH;
        gemm_phase<1>(As, Ws, Abase, xt);
        gridbar(base + ++bc);
        epi_phase<1>(xt);
        gridbar(base + ++bc);
        gemm_phase<2>(As, Ws, Abase, xt);
        gridbar(base + ++bc);
        epi_phase<2>(xt);
        gridbar(base + ++bc);
    }

    for (int i = gt; i < BD; i += GT) {
        out[i]          = g_h [i];
        out[BD + i]     = g_c [i];
        out[2 * BD + i] = g_h2[i];
        out[3 * BD + i] = g_c2[i];
    }
}

extern "C" void kernel_launch(void* const* d_in, const int* in_sizes, int n_in,
                              void* d_out, int out_size)
{
    (void)in_sizes; (void)n_in; (void)out_size;
    const int*   x   = (const int*)  d_in[0];
    const float* emb = (const float*)d_in[1];
    const float* Wih = (const float*)d_in[2];
    const float* Whh = (const float*)d_in[3];
    const float* bih = (const float*)d_in[4];
    const float* bhh = (const float*)d_in[5];
    const float* h0  = (const float*)d_in[6];
    const float* c0  = (const float*)d_in[7];
    const float* h02 = (const float*)d_in[8];
    const float* c02 = (const float*)d_in[9];

    const int smem = (3 * 128 * LDS_S + 3 * 256 * LDS_S) * 4 + 128 * 8;  // 166,912 B
    cudaFuncSetAttribute(lstm_persist, cudaFuncAttributeMaxDynamicSharedMemorySize, smem);

    lstm_persist<<<NCTA, NTHR, smem>>>(x, emb, Wih, Whh, bih, bhh,
                                       h0, c0, h02, c02, (float*)d_out);
}